// round 5
// baseline (speedup 1.0000x reference)
#include <cuda_runtime.h>

// SRLoss: loss = mean((inp - avgpool10x10(output))^2) - mean(t*log(o') + (1-t)*log(1-o'))
// output/target: [32,1,1280,1280] f32; inp: [32,1,128,128] f32; out: scalar f32 (1,1).

constexpr int Bc = 32;
constexpr int Hc = 1280;
constexpr int Wc = 1280;
constexpr int Sc = 10;          // pool scale
constexpr int hc = Hc / Sc;     // 128
constexpr int wc = Wc / Sc;     // 128
constexpr int W4 = Wc / 4;      // 320 float4 per row
constexpr int NBLK = Bc * hc;   // 4096 CTAs

__device__ float g_part_bce[NBLK];
__device__ float g_part_mse[NBLK];

__device__ __forceinline__ float bce_term(float o, float t) {
    // om = (o==0) ? 1e-20 : o ;  oc = (1-o==0) ? 1e-20 : 1-o
    float om  = (o == 0.0f) ? 1e-20f : o;
    float ocr = 1.0f - o;
    float oc  = (ocr == 0.0f) ? 1e-20f : ocr;
    // accumulate +(t*log(om) + (1-t)*log(oc)); negated in the finalize kernel
    return fmaf(t, __logf(om), (1.0f - t) * __logf(oc));
}

__global__ __launch_bounds__(256) void srloss_main(
    const float4* __restrict__ out4,
    const float4* __restrict__ tgt4,
    const float*  __restrict__ inp)
{
    const int blk = blockIdx.x;          // b*128 + g
    const int b   = blk >> 7;
    const int g   = blk & 127;
    const int tid = threadIdx.x;

    __shared__ float colsum[Wc];         // per-column sums over the 10 rows
    __shared__ float red_b[256];
    __shared__ float red_m[256];

    const int base = (b * Hc + g * Sc) * W4;   // float4 index of tile start (fits int)

    float bce = 0.0f;
    float4 acc0 = make_float4(0.f, 0.f, 0.f, 0.f);
    float4 acc1 = make_float4(0.f, 0.f, 0.f, 0.f);
    const int i0 = tid;
    const int i1 = tid + 256;
    const bool has1 = (i1 < W4);         // true only for tids 0..63 (warps 0-1): warp-uniform

    #pragma unroll
    for (int r = 0; r < Sc; r++) {
        const int rb = base + r * W4;
        float4 o = out4[rb + i0];
        float4 t = tgt4[rb + i0];
        bce += bce_term(o.x, t.x) + bce_term(o.y, t.y)
             + bce_term(o.z, t.z) + bce_term(o.w, t.w);
        acc0.x += o.x; acc0.y += o.y; acc0.z += o.z; acc0.w += o.w;
        if (has1) {
            float4 o2 = out4[rb + i1];
            float4 t2 = tgt4[rb + i1];
            bce += bce_term(o2.x, t2.x) + bce_term(o2.y, t2.y)
                 + bce_term(o2.z, t2.z) + bce_term(o2.w, t2.w);
            acc1.x += o2.x; acc1.y += o2.y; acc1.z += o2.z; acc1.w += o2.w;
        }
    }

    reinterpret_cast<float4*>(colsum)[i0] = acc0;
    if (has1) reinterpret_cast<float4*>(colsum)[i1] = acc1;
    __syncthreads();

    float mse = 0.0f;
    if (tid < wc) {
        float s = 0.0f;
        #pragma unroll
        for (int c = 0; c < Sc; c++) s += colsum[tid * Sc + c];
        const float pooled = s * (1.0f / (Sc * Sc));
        const float v = inp[(b * hc + g) * wc + tid];
        const float d = v - pooled;
        mse = d * d;
    }

    red_b[tid] = bce;
    red_m[tid] = mse;
    __syncthreads();
    #pragma unroll
    for (int s = 128; s > 0; s >>= 1) {
        if (tid < s) {
            red_b[tid] += red_b[tid + s];
            red_m[tid] += red_m[tid + s];
        }
        __syncthreads();
    }
    if (tid == 0) {
        g_part_bce[blk] = red_b[0];
        g_part_mse[blk] = red_m[0];
    }
}

__global__ __launch_bounds__(256) void srloss_finalize(float* __restrict__ out, int out_size)
{
    __shared__ double rb[256];
    __shared__ double rm[256];
    const int tid = threadIdx.x;
    double sb = 0.0, sm = 0.0;
    for (int i = tid; i < NBLK; i += 256) {
        sb += (double)g_part_bce[i];
        sm += (double)g_part_mse[i];
    }
    rb[tid] = sb;
    rm[tid] = sm;
    __syncthreads();
    #pragma unroll
    for (int s = 128; s > 0; s >>= 1) {
        if (tid < s) { rb[tid] += rb[tid + s]; rm[tid] += rm[tid + s]; }
        __syncthreads();
    }
    if (tid == 0) {
        const double n_bce = (double)Bc * Hc * Wc;
        const double n_mse = (double)Bc * hc * wc;
        const double loss = rm[0] / n_mse - rb[0] / n_bce;
        const float lf = (float)loss;
        for (int i = 0; i < out_size; i++) out[i] = lf;
    }
}

extern "C" void kernel_launch(void* const* d_in, const int* in_sizes, int n_in,
                              void* d_out, int out_size)
{
    const float4* out4 = (const float4*)d_in[0];   // output [32,1,1280,1280]
    const float4* tgt4 = (const float4*)d_in[1];   // target [32,1,1280,1280]
    const float*  inp  = (const float*)d_in[2];    // inp    [32,1,128,128]
    float* out = (float*)d_out;

    srloss_main<<<NBLK, 256>>>(out4, tgt4, inp);
    srloss_finalize<<<1, 256>>>(out, out_size);
}

// round 7
// speedup vs baseline: 1.3270x; 1.3270x over previous
#include <cuda_runtime.h>

// SRLoss: loss = mean((inp - avgpool10x10(output))^2) - mean(t*log(o') + (1-t)*log(1-o'))
// output/target: [32,1,1280,1280] f32; inp: [32,1,128,128] f32; out: scalar f32 (1,1).
// Single fused kernel: per-CTA tile reduction + last-block final reduction.

constexpr int Bc = 32;
constexpr int Hc = 1280;
constexpr int Wc = 1280;
constexpr int Sc = 10;          // pool scale
constexpr int hc = Hc / Sc;     // 128
constexpr int wc = Wc / Sc;     // 128
constexpr int W4 = Wc / 4;      // 320 float4 per row
constexpr int NBLK = Bc * hc;   // 4096 CTAs
constexpr int NT   = 320;       // 10 warps, one float4 per thread per row
constexpr int NW   = NT / 32;   // 10 warps

__device__ float g_part_bce[NBLK];
__device__ float g_part_mse[NBLK];
__device__ unsigned int g_count = 0;   // wraps to 0 every NBLK increments

__device__ __forceinline__ float bce_term(float o, float t) {
    // om = (o==0) ? 1e-20 : o ;  oc = (1-o==0) ? 1e-20 : 1-o
    float om  = (o == 0.0f) ? 1e-20f : o;
    float ocr = 1.0f - o;
    float oc  = (ocr == 0.0f) ? 1e-20f : ocr;
    // accumulate +(t*log(om) + (1-t)*log(oc)); negated at the end
    return fmaf(t, __logf(om), (1.0f - t) * __logf(oc));
}

__global__ __launch_bounds__(NT) void srloss_fused(
    const float4* __restrict__ out4,
    const float4* __restrict__ tgt4,
    const float*  __restrict__ inp,
    float* __restrict__ out, int out_size)
{
    const int blk  = blockIdx.x;         // b*128 + g
    const int b    = blk >> 7;
    const int g    = blk & 127;
    const int tid  = threadIdx.x;        // 0..319
    const int lane = tid & 31;
    const int wid  = tid >> 5;           // 0..9

    __shared__ float colsum[Wc];         // per-column sums over the 10 rows
    __shared__ float warp_b[NW];
    __shared__ float warp_m[NW];
    __shared__ bool  is_last;

    const int base = (b * Hc + g * Sc) * W4;   // float4 index of tile start

    // prefetch the inp value this thread needs for MSE (tid < 128 only)
    float vin = 0.0f;
    if (tid < wc) vin = __ldg(&inp[(b * hc + g) * wc + tid]);

    float bce = 0.0f;
    float4 acc = make_float4(0.f, 0.f, 0.f, 0.f);

    #pragma unroll
    for (int r = 0; r < Sc; r++) {
        const int idx = base + r * W4 + tid;
        float4 o = __ldcs(&out4[idx]);
        float4 t = __ldcs(&tgt4[idx]);
        bce += bce_term(o.x, t.x) + bce_term(o.y, t.y)
             + bce_term(o.z, t.z) + bce_term(o.w, t.w);
        acc.x += o.x; acc.y += o.y; acc.z += o.z; acc.w += o.w;
    }

    reinterpret_cast<float4*>(colsum)[tid] = acc;
    __syncthreads();

    float mse = 0.0f;
    if (tid < wc) {
        float s = 0.0f;
        #pragma unroll
        for (int c = 0; c < Sc; c++) s += colsum[tid * Sc + c];
        const float d = vin - s * (1.0f / (Sc * Sc));
        mse = d * d;
    }

    // warp-level reductions (fixed shuffle order -> deterministic)
    #pragma unroll
    for (int off = 16; off > 0; off >>= 1) {
        bce += __shfl_xor_sync(0xFFFFFFFFu, bce, off);
        mse += __shfl_xor_sync(0xFFFFFFFFu, mse, off);
    }
    if (lane == 0) { warp_b[wid] = bce; warp_m[wid] = mse; }
    __syncthreads();

    if (tid == 0) {
        float sb = 0.f, sm = 0.f;
        #pragma unroll
        for (int w = 0; w < NW; w++) { sb += warp_b[w]; sm += warp_m[w]; }
        g_part_bce[blk] = sb;
        g_part_mse[blk] = sm;
    }

    // ----- last-block final reduction -----
    __threadfence();                       // make partials visible device-wide
    if (tid == 0) {
        unsigned int old = atomicInc(&g_count, NBLK - 1);  // wraps -> self-resets per launch
        is_last = (old == NBLK - 1);
    }
    __syncthreads();
    if (!is_last) return;

    __shared__ double dwb[NW];
    __shared__ double dwm[NW];

    double sb = 0.0, sm = 0.0;
    for (int i = tid; i < NBLK; i += NT) {
        sb += (double)__ldcg(&g_part_bce[i]);   // L2 reads: skip possibly-stale L1
        sm += (double)__ldcg(&g_part_mse[i]);
    }
    #pragma unroll
    for (int off = 16; off > 0; off >>= 1) {
        sb += __shfl_xor_sync(0xFFFFFFFFu, sb, off);
        sm += __shfl_xor_sync(0xFFFFFFFFu, sm, off);
    }
    if (lane == 0) { dwb[wid] = sb; dwm[wid] = sm; }
    __syncthreads();

    if (tid == 0) {
        double tb = 0.0, tm = 0.0;
        #pragma unroll
        for (int w = 0; w < NW; w++) { tb += dwb[w]; tm += dwm[w]; }
        const double n_bce = (double)Bc * Hc * Wc;
        const double n_mse = (double)Bc * hc * wc;
        const float lf = (float)(tm / n_mse - tb / n_bce);
        for (int i = 0; i < out_size; i++) out[i] = lf;
    }
}

extern "C" void kernel_launch(void* const* d_in, const int* in_sizes, int n_in,
                              void* d_out, int out_size)
{
    const float4* out4 = (const float4*)d_in[0];   // output [32,1,1280,1280]
    const float4* tgt4 = (const float4*)d_in[1];   // target [32,1,1280,1280]
    const float*  inp  = (const float*)d_in[2];    // inp    [32,1,128,128]
    float* out = (float*)d_out;

    srloss_fused<<<NBLK, NT>>>(out4, tgt4, inp, out, out_size);
}